// round 8
// baseline (speedup 1.0000x reference)
#include <cuda_runtime.h>
#include <cuda_fp16.h>
#include <cstdint>

// Problem constants
#define BB   8
#define CC   256
#define HH   64
#define WWW  64
#define HWSZ 4096
#define K2C  9
#define OO   256
#define KTOT (K2C * CC)          // 2304
#define NKB  (KTOT / 64)         // 36 slabs of K=64

// Scratch (device globals — no allocation allowed)
__device__ __half   g_xTh[BB * HWSZ * CC];    // x transposed fp16: [B][HW][C]
__device__ uint32_t g_WkFH[OO * KTOT / 2];    // weights fp16x2, mma-fragment order
__device__ uint2    g_idx16[BB * K2C * HWSZ]; // 4 corner indices packed u16
__device__ float4   g_wgt[BB * K2C * HWSZ];   // 4 bilinear weights (0 if OOB)

// ---------------------------------------------------------------------------
// Kernel A: transpose x [B][C][HW] -> g_xTh [B][HW][C] (fp16)
// ---------------------------------------------------------------------------
__global__ void transpose_x_kernel(const float* __restrict__ x) {
    __shared__ __align__(16) float tile[32][33];
    int b   = blockIdx.z;
    int hw0 = blockIdx.x * 32;
    int c0  = blockIdx.y * 32;
    int tx = threadIdx.x, ty = threadIdx.y;
    const float* xb = x + (size_t)b * CC * HWSZ;
#pragma unroll
    for (int i = 0; i < 4; i++) {
        int c = c0 + ty + i * 8;
        tile[ty + i * 8][tx] = xb[(size_t)c * HWSZ + hw0 + tx];
    }
    __syncthreads();
    __half* xt = g_xTh + (size_t)b * HWSZ * CC;
#pragma unroll
    for (int i = 0; i < 4; i++) {
        int hw = hw0 + ty + i * 8;
        xt[(size_t)hw * CC + c0 + tx] = __float2half(tile[tx][ty + i * 8]);
    }
}

// ---------------------------------------------------------------------------
// Kernel B: build bilinear meta (packed u16 indices + fp32 weights)
// ---------------------------------------------------------------------------
__device__ __forceinline__ int clamp63(int v) { return v < 0 ? 0 : (v > 63 ? 63 : v); }

__global__ void build_meta_kernel(const float* __restrict__ offset) {
    int t = blockIdx.x * blockDim.x + threadIdx.x;
    int p  = t & (HWSZ - 1);
    int bk = t >> 12;
    int k2 = bk % K2C;
    int b  = bk / K2C;
    int ho = p >> 6, wo = p & 63;
    int ky = k2 / 3, kx = k2 % 3;
    const float* ob = offset + (size_t)b * 2 * K2C * HWSZ;
    float dy = ob[(size_t)(k2 * 2 + 0) * HWSZ + p];
    float dx = ob[(size_t)(k2 * 2 + 1) * HWSZ + p];
    float py = (float)(ho - 1 + ky) + dy;
    float px = (float)(wo - 1 + kx) + dx;
    float y0f = floorf(py), x0f = floorf(px);
    int   y0  = (int)y0f,  x0  = (int)x0f;
    float fy = py - y0f,   fx = px - x0f;
    int ys[2] = { y0, y0 + 1 }, xs[2] = { x0, x0 + 1 };
    float wy[2] = { 1.0f - fy, fy }, wx[2] = { 1.0f - fx, fx };
    uint32_t idx[4]; float w[4];
#pragma unroll
    for (int j = 0; j < 4; j++) {
        int yy = ys[j >> 1], xx = xs[j & 1];
        bool valid = (yy >= 0) && (yy < HH) && (xx >= 0) && (xx < WWW);
        w[j]   = valid ? (wy[j >> 1] * wx[j & 1]) : 0.0f;
        idx[j] = (uint32_t)(clamp63(yy) * WWW + clamp63(xx));
    }
    g_idx16[t] = make_uint2(idx[0] | (idx[1] << 16), idx[2] | (idx[3] << 16));
    g_wgt[t]   = make_float4(w[0], w[1], w[2], w[3]);
}

// ---------------------------------------------------------------------------
// Kernel B2: weight -> g_WkFH fp16x2 in m16n8k16 fragment order.
// ---------------------------------------------------------------------------
__global__ void prep_w_kernel(const float* __restrict__ weight) {
    int t = blockIdx.x * blockDim.x + threadIdx.x;   // < OO*KTOT/2
    int e    = t & 3;
    int lane = (t >> 2) & 31;
    int ks   = (t >> 7) & 3;
    int mi   = (t >> 9) & 3;
    int kb   = (t >> 11) % NKB;
    int half = (t >> 11) / NKB;
    int wm = half & 1, ohalf = half >> 1;
    int row = wm * 64 + mi * 16 + (lane >> 2) + (e & 1) * 8;
    int kg  = kb * 64 + ks * 16 + (e >> 1) * 8 + 2 * (lane & 3);
    int o  = ohalf * 128 + row;
    int k2 = kg >> 8, c = kg & 255;
    float w0 = weight[((size_t)o * CC + c) * K2C + k2];
    float w1 = weight[((size_t)o * CC + c + 1) * K2C + k2];
    __half2 h = __floats2half2_rn(w0, w1);
    g_WkFH[t] = *(const uint32_t*)&h;
}

// ---------------------------------------------------------------------------
// Kernel C: fused fp16 gather + fp16 m16n8k16 mma, pipelined, XOR-swizzled B.
//   B_s word layout: word = n*32 + (kw ^ ((n&7)<<2)), kw = k-pair index 0..31.
// ---------------------------------------------------------------------------
__global__ __launch_bounds__(256, 2)
void dconv_mma_kernel(float* __restrict__ out) {
    __shared__ __align__(16) uint32_t B_s[2][128 * 32];
    __shared__ __align__(16) uint2  sIdx[2][128];
    __shared__ __align__(16) float4 sWb[2][128];

    int tid  = threadIdx.x;
    int lane = tid & 31;
    int wid  = tid >> 5;
    int bx = blockIdx.x;
    int b  = bx >> 6;
    int ohalf = (bx >> 5) & 1;
    int o0 = ohalf * 128;
    int p0 = (bx & 31) * 128;

    int wm = wid & 1;
    int wn = wid >> 1;

    float acc[4][4][4];
#pragma unroll
    for (int mi = 0; mi < 4; mi++)
#pragma unroll
        for (int ni = 0; ni < 4; ni++)
#pragma unroll
            for (int r = 0; r < 4; r++) acc[mi][ni][r] = 0.0f;

    const __half* xTb = g_xTh + (size_t)b * HWSZ * CC;
    const uint4* wfh = (const uint4*)(g_WkFH + (size_t)(ohalf * 2 + wm) * NKB * 2048);

    uint32_t hreg[16];

    // ---- prologue: meta for k2=0, gather slab 0
    if (tid < 128) {
        size_t mi0 = ((size_t)(b * K2C) * HWSZ) + p0 + tid;
        sIdx[0][tid] = g_idx16[mi0];
        sWb[0][tid]  = g_wgt[mi0];
    }
    __syncthreads();
    {
        const __half* xc = xTb + 2 * lane;
#pragma unroll
        for (int q = 0; q < 16; q++) {
            int p = wid * 16 + q;
            uint2  iv = sIdx[0][p];
            float4 wv = sWb[0][p];
            float2 u0 = __half22float2(*(const __half2*)(xc + (size_t)(iv.x & 0xFFFF) * CC));
            float2 u1 = __half22float2(*(const __half2*)(xc + (size_t)(iv.x >> 16)    * CC));
            float2 u2 = __half22float2(*(const __half2*)(xc + (size_t)(iv.y & 0xFFFF) * CC));
            float2 u3 = __half22float2(*(const __half2*)(xc + (size_t)(iv.y >> 16)    * CC));
            float rx = wv.x * u0.x + wv.y * u1.x + wv.z * u2.x + wv.w * u3.x;
            float ry = wv.x * u0.y + wv.y * u1.y + wv.z * u2.y + wv.w * u3.y;
            __half2 h = __floats2half2_rn(rx, ry);
            hreg[q] = *(const uint32_t*)&h;
        }
#pragma unroll
        for (int q = 0; q < 16; q++) {
            int p = wid * 16 + q;
            B_s[0][p * 32 + (lane ^ ((p & 7) << 2))] = hreg[q];
        }
    }

    for (int kb = 0; kb < NKB; kb++) {
        __syncthreads();          // B_s[kb&1] ready; all MMA(kb-1) done
        int nkb = kb + 1;
        if (nkb < NKB && (nkb & 3) == 0) {
            int nk2 = nkb >> 2;
            if (tid < 128) {
                size_t mi0 = ((size_t)(b * K2C + nk2) * HWSZ) + p0 + tid;
                sIdx[nk2 & 1][tid] = g_idx16[mi0];
                sWb[nk2 & 1][tid]  = g_wgt[mi0];
            }
            __syncthreads();
        }

        // ---- gather slab kb+1 into registers (overlaps MMA below)
        if (nkb < NKB) {
            int mb = (nkb >> 2) & 1;
            int c0 = (nkb & 3) * 64;
            const __half* xc = xTb + c0 + 2 * lane;
#pragma unroll
            for (int q = 0; q < 16; q++) {
                int p = wid * 16 + q;
                uint2  iv = sIdx[mb][p];
                float4 wv = sWb[mb][p];
                float2 u0 = __half22float2(*(const __half2*)(xc + (size_t)(iv.x & 0xFFFF) * CC));
                float2 u1 = __half22float2(*(const __half2*)(xc + (size_t)(iv.x >> 16)    * CC));
                float2 u2 = __half22float2(*(const __half2*)(xc + (size_t)(iv.y & 0xFFFF) * CC));
                float2 u3 = __half22float2(*(const __half2*)(xc + (size_t)(iv.y >> 16)    * CC));
                float rx = wv.x * u0.x + wv.y * u1.x + wv.z * u2.x + wv.w * u3.x;
                float ry = wv.x * u0.y + wv.y * u1.y + wv.z * u2.y + wv.w * u3.y;
                __half2 h = __floats2half2_rn(rx, ry);
                hreg[q] = *(const uint32_t*)&h;
            }
        }

        // ---- MMA on slab kb: 4 k-steps of 16
        {
            const uint4* wkc = wfh + (size_t)kb * 512;
            const uint32_t* Bb = &B_s[kb & 1][0];
#pragma unroll
            for (int ks = 0; ks < 4; ks++) {
                uint4 afr[4];
#pragma unroll
                for (int mi = 0; mi < 4; mi++)
                    afr[mi] = wkc[(mi * 4 + ks) * 32 + lane];
                uint32_t bfr[4][2];
#pragma unroll
                for (int ni = 0; ni < 4; ni++) {
                    int n  = wn * 32 + ni * 8 + (lane >> 2);
                    int sw = (n & 7) << 2;
                    int kw = ks * 8 + (lane & 3);
                    bfr[ni][0] = Bb[n * 32 + (kw ^ sw)];
                    bfr[ni][1] = Bb[n * 32 + ((kw + 4) ^ sw)];
                }
#pragma unroll
                for (int mi = 0; mi < 4; mi++)
#pragma unroll
                    for (int ni = 0; ni < 4; ni++) {
                        asm volatile(
                            "mma.sync.aligned.m16n8k16.row.col.f32.f16.f16.f32 "
                            "{%0,%1,%2,%3}, {%4,%5,%6,%7}, {%8,%9}, {%0,%1,%2,%3};"
                            : "+f"(acc[mi][ni][0]), "+f"(acc[mi][ni][1]),
                              "+f"(acc[mi][ni][2]), "+f"(acc[mi][ni][3])
                            : "r"(afr[mi].x), "r"(afr[mi].y), "r"(afr[mi].z), "r"(afr[mi].w),
                              "r"(bfr[ni][0]), "r"(bfr[ni][1]));
                    }
            }
        }

        // ---- stage gathered slab kb+1 (other buffer)
        if (nkb < NKB) {
#pragma unroll
            for (int q = 0; q < 16; q++) {
                int p = wid * 16 + q;
                B_s[nkb & 1][p * 32 + (lane ^ ((p & 7) << 2))] = hreg[q];
            }
        }
    }

    // ---- epilogue
    {
        int r  = lane >> 2;
        int cl = (lane & 3) * 2;
#pragma unroll
        for (int mi = 0; mi < 4; mi++) {
            int m = wm * 64 + mi * 16 + r;
            float* op = out + ((size_t)b * OO + (o0 + m)) * HWSZ + p0;
#pragma unroll
            for (int ni = 0; ni < 4; ni++) {
                int n = wn * 32 + ni * 8 + cl;
                *(float2*)(op + n) =
                    make_float2(acc[mi][ni][0], acc[mi][ni][1]);
                *(float2*)(op + 8 * HWSZ + n) =
                    make_float2(acc[mi][ni][2], acc[mi][ni][3]);
            }
        }
    }
}

// ---------------------------------------------------------------------------
extern "C" void kernel_launch(void* const* d_in, const int* in_sizes, int n_in,
                              void* d_out, int out_size) {
    const float* x      = (const float*)d_in[0];
    const float* offset = (const float*)d_in[1];
    const float* weight = (const float*)d_in[2];
    float* out = (float*)d_out;

    transpose_x_kernel<<<dim3(HWSZ / 32, CC / 32, BB), dim3(32, 8)>>>(x);
    build_meta_kernel<<<(BB * K2C * HWSZ) / 256, 256>>>(offset);
    prep_w_kernel<<<(OO * KTOT / 2) / 256, 256>>>(weight);
    dconv_mma_kernel<<<BB * 64, 256>>>(out);
}

// round 9
// speedup vs baseline: 1.7632x; 1.7632x over previous
#include <cuda_runtime.h>
#include <cuda_fp16.h>
#include <cstdint>

// Problem constants
#define BB   8
#define CC   256
#define HH   64
#define WWW  64
#define HWSZ 4096
#define K2C  9
#define OO   256
#define KTOT (K2C * CC)          // 2304
#define NKB  (KTOT / 64)         // 36 slabs of K=64
#define SW   36                  // B smem row stride in fp16x2 words

// Scratch (device globals — no allocation allowed)
__device__ __half   g_xTh[BB * HWSZ * CC];    // x transposed fp16: [B][HW][C]
__device__ uint32_t g_WkFH[OO * KTOT / 2];    // weights fp16x2, mma-fragment order
__device__ int4     g_off[BB * K2C * HWSZ];   // 4 corner BYTE offsets (idx*CC*2)
__device__ uint4    g_wh[BB * K2C * HWSZ];    // 4 bilinear weights as half2 bcast

// ---------------------------------------------------------------------------
// Kernel A: transpose x [B][C][HW] -> g_xTh [B][HW][C] (fp16)
// ---------------------------------------------------------------------------
__global__ void transpose_x_kernel(const float* __restrict__ x) {
    __shared__ __align__(16) float tile[32][33];
    int b   = blockIdx.z;
    int hw0 = blockIdx.x * 32;
    int c0  = blockIdx.y * 32;
    int tx = threadIdx.x, ty = threadIdx.y;
    const float* xb = x + (size_t)b * CC * HWSZ;
#pragma unroll
    for (int i = 0; i < 4; i++) {
        int c = c0 + ty + i * 8;
        tile[ty + i * 8][tx] = xb[(size_t)c * HWSZ + hw0 + tx];
    }
    __syncthreads();
    __half* xt = g_xTh + (size_t)b * HWSZ * CC;
#pragma unroll
    for (int i = 0; i < 4; i++) {
        int hw = hw0 + ty + i * 8;
        xt[(size_t)hw * CC + c0 + tx] = __float2half(tile[tx][ty + i * 8]);
    }
}

// ---------------------------------------------------------------------------
// Kernel B: build bilinear meta (byte offsets + half2-broadcast weights)
// ---------------------------------------------------------------------------
__device__ __forceinline__ int clamp63(int v) { return v < 0 ? 0 : (v > 63 ? 63 : v); }

__global__ void build_meta_kernel(const float* __restrict__ offset) {
    int t = blockIdx.x * blockDim.x + threadIdx.x;
    int p  = t & (HWSZ - 1);
    int bk = t >> 12;
    int k2 = bk % K2C;
    int b  = bk / K2C;
    int ho = p >> 6, wo = p & 63;
    int ky = k2 / 3, kx = k2 % 3;
    const float* ob = offset + (size_t)b * 2 * K2C * HWSZ;
    float dy = ob[(size_t)(k2 * 2 + 0) * HWSZ + p];
    float dx = ob[(size_t)(k2 * 2 + 1) * HWSZ + p];
    float py = (float)(ho - 1 + ky) + dy;
    float px = (float)(wo - 1 + kx) + dx;
    float y0f = floorf(py), x0f = floorf(px);
    int   y0  = (int)y0f,  x0  = (int)x0f;
    float fy = py - y0f,   fx = px - x0f;
    int ys[2] = { y0, y0 + 1 }, xs[2] = { x0, x0 + 1 };
    float wy[2] = { 1.0f - fy, fy }, wx[2] = { 1.0f - fx, fx };
    int off[4]; uint32_t wh[4];
#pragma unroll
    for (int j = 0; j < 4; j++) {
        int yy = ys[j >> 1], xx = xs[j & 1];
        bool valid = (yy >= 0) && (yy < HH) && (xx >= 0) && (xx < WWW);
        float w = valid ? (wy[j >> 1] * wx[j & 1]) : 0.0f;
        __half2 h = __float2half2_rn(w);
        wh[j]  = *(const uint32_t*)&h;
        off[j] = (clamp63(yy) * WWW + clamp63(xx)) * (CC * 2);   // bytes
    }
    g_off[t] = make_int4(off[0], off[1], off[2], off[3]);
    g_wh[t]  = make_uint4(wh[0], wh[1], wh[2], wh[3]);
}

// ---------------------------------------------------------------------------
// Kernel B2: weight -> g_WkFH fp16x2 in m16n8k16 fragment order.
// ---------------------------------------------------------------------------
__global__ void prep_w_kernel(const float* __restrict__ weight) {
    int t = blockIdx.x * blockDim.x + threadIdx.x;   // < OO*KTOT/2
    int e    = t & 3;
    int lane = (t >> 2) & 31;
    int ks   = (t >> 7) & 3;
    int mi   = (t >> 9) & 3;
    int kb   = (t >> 11) % NKB;
    int half = (t >> 11) / NKB;
    int wm = half & 1, ohalf = half >> 1;
    int row = wm * 64 + mi * 16 + (lane >> 2) + (e & 1) * 8;
    int kg  = kb * 64 + ks * 16 + (e >> 1) * 8 + 2 * (lane & 3);
    int o  = ohalf * 128 + row;
    int k2 = kg >> 8, c = kg & 255;
    float w0 = weight[((size_t)o * CC + c) * K2C + k2];
    float w1 = weight[((size_t)o * CC + c + 1) * K2C + k2];
    __half2 h = __floats2half2_rn(w0, w1);
    g_WkFH[t] = *(const uint32_t*)&h;
}

// ---------------------------------------------------------------------------
// Kernel C: fused HFMA2 gather + fp16 m16n8k16 mma, pipelined.
//   B smem: padded stride 36 words (proven conflict-free, zero-ALU addressing).
// ---------------------------------------------------------------------------
__global__ __launch_bounds__(256, 2)
void dconv_mma_kernel(float* __restrict__ out) {
    __shared__ __align__(16) uint32_t B_s[2][128 * SW];
    __shared__ __align__(16) int4  sOff[2][128];
    __shared__ __align__(16) uint4 sWh[2][128];

    int tid  = threadIdx.x;
    int lane = tid & 31;
    int wid  = tid >> 5;
    int bx = blockIdx.x;
    int b  = bx >> 6;
    int ohalf = (bx >> 5) & 1;
    int o0 = ohalf * 128;
    int p0 = (bx & 31) * 128;

    int wm = wid & 1;
    int wn = wid >> 1;

    float acc[4][4][4];
#pragma unroll
    for (int mi = 0; mi < 4; mi++)
#pragma unroll
        for (int ni = 0; ni < 4; ni++)
#pragma unroll
            for (int r = 0; r < 4; r++) acc[mi][ni][r] = 0.0f;

    const __half* xTb = g_xTh + (size_t)b * HWSZ * CC;
    const uint4* wfh = (const uint4*)(g_WkFH + (size_t)(ohalf * 2 + wm) * NKB * 2048);

    uint32_t hreg[16];

    // ---- prologue: meta for k2=0, gather slab 0
    if (tid < 128) {
        size_t mi0 = ((size_t)(b * K2C) * HWSZ) + p0 + tid;
        sOff[0][tid] = g_off[mi0];
        sWh[0][tid]  = g_wh[mi0];
    }
    __syncthreads();
    {
        const char* xc = (const char*)(xTb + 2 * lane);
#pragma unroll
        for (int q = 0; q < 16; q++) {
            int p = wid * 16 + q;
            int4  ov = sOff[0][p];
            uint4 wv = sWh[0][p];
            __half2 u0 = *(const __half2*)(xc + ov.x);
            __half2 u1 = *(const __half2*)(xc + ov.y);
            __half2 u2 = *(const __half2*)(xc + ov.z);
            __half2 u3 = *(const __half2*)(xc + ov.w);
            __half2 a = __hmul2(*(const __half2*)&wv.x, u0);
            a = __hfma2(*(const __half2*)&wv.y, u1, a);
            a = __hfma2(*(const __half2*)&wv.z, u2, a);
            a = __hfma2(*(const __half2*)&wv.w, u3, a);
            hreg[q] = *(const uint32_t*)&a;
        }
#pragma unroll
        for (int q = 0; q < 16; q++)
            B_s[0][(wid * 16 + q) * SW + lane] = hreg[q];
    }

    for (int kb = 0; kb < NKB; kb++) {
        __syncthreads();          // B_s[kb&1] ready; all MMA(kb-1) done
        int nkb = kb + 1;
        if (nkb < NKB && (nkb & 3) == 0) {
            int nk2 = nkb >> 2;
            if (tid < 128) {
                size_t mi0 = ((size_t)(b * K2C + nk2) * HWSZ) + p0 + tid;
                sOff[nk2 & 1][tid] = g_off[mi0];
                sWh[nk2 & 1][tid]  = g_wh[mi0];
            }
            __syncthreads();
        }

        // ---- gather slab kb+1 into registers (overlaps MMA below)
        if (nkb < NKB) {
            int mb = (nkb >> 2) & 1;
            int c0 = (nkb & 3) * 64;
            const char* xc = (const char*)(xTb + c0 + 2 * lane);
#pragma unroll
            for (int q = 0; q < 16; q++) {
                int p = wid * 16 + q;
                int4  ov = sOff[mb][p];
                uint4 wv = sWh[mb][p];
                __half2 u0 = *(const __half2*)(xc + ov.x);
                __half2 u1 = *(const __half2*)(xc + ov.y);
                __half2 u2 = *(const __half2*)(xc + ov.z);
                __half2 u3 = *(const __half2*)(xc + ov.w);
                __half2 a = __hmul2(*(const __half2*)&wv.x, u0);
                a = __hfma2(*(const __half2*)&wv.y, u1, a);
                a = __hfma2(*(const __half2*)&wv.z, u2, a);
                a = __hfma2(*(const __half2*)&wv.w, u3, a);
                hreg[q] = *(const uint32_t*)&a;
            }
        }

        // ---- MMA on slab kb: 4 k-steps of 16
        {
            const uint4* wkc = wfh + (size_t)kb * 512;
            const uint32_t* Bb = &B_s[kb & 1][0];
#pragma unroll
            for (int ks = 0; ks < 4; ks++) {
                uint4 afr[4];
#pragma unroll
                for (int mi = 0; mi < 4; mi++)
                    afr[mi] = wkc[(mi * 4 + ks) * 32 + lane];
                uint32_t bfr[4][2];
#pragma unroll
                for (int ni = 0; ni < 4; ni++) {
                    int base = (wn * 32 + ni * 8 + (lane >> 2)) * SW + ks * 8 + (lane & 3);
                    bfr[ni][0] = Bb[base];
                    bfr[ni][1] = Bb[base + 4];
                }
#pragma unroll
                for (int mi = 0; mi < 4; mi++)
#pragma unroll
                    for (int ni = 0; ni < 4; ni++) {
                        asm volatile(
                            "mma.sync.aligned.m16n8k16.row.col.f32.f16.f16.f32 "
                            "{%0,%1,%2,%3}, {%4,%5,%6,%7}, {%8,%9}, {%0,%1,%2,%3};"
                            : "+f"(acc[mi][ni][0]), "+f"(acc[mi][ni][1]),
                              "+f"(acc[mi][ni][2]), "+f"(acc[mi][ni][3])
                            : "r"(afr[mi].x), "r"(afr[mi].y), "r"(afr[mi].z), "r"(afr[mi].w),
                              "r"(bfr[ni][0]), "r"(bfr[ni][1]));
                    }
            }
        }

        // ---- stage gathered slab kb+1 (other buffer)
        if (nkb < NKB) {
#pragma unroll
            for (int q = 0; q < 16; q++)
                B_s[nkb & 1][(wid * 16 + q) * SW + lane] = hreg[q];
        }
    }

    // ---- epilogue
    {
        int r  = lane >> 2;
        int cl = (lane & 3) * 2;
#pragma unroll
        for (int mi = 0; mi < 4; mi++) {
            int m = wm * 64 + mi * 16 + r;
            float* op = out + ((size_t)b * OO + (o0 + m)) * HWSZ + p0;
#pragma unroll
            for (int ni = 0; ni < 4; ni++) {
                int n = wn * 32 + ni * 8 + cl;
                *(float2*)(op + n) =
                    make_float2(acc[mi][ni][0], acc[mi][ni][1]);
                *(float2*)(op + 8 * HWSZ + n) =
                    make_float2(acc[mi][ni][2], acc[mi][ni][3]);
            }
        }
    }
}

// ---------------------------------------------------------------------------
extern "C" void kernel_launch(void* const* d_in, const int* in_sizes, int n_in,
                              void* d_out, int out_size) {
    const float* x      = (const float*)d_in[0];
    const float* offset = (const float*)d_in[1];
    const float* weight = (const float*)d_in[2];
    float* out = (float*)d_out;

    transpose_x_kernel<<<dim3(HWSZ / 32, CC / 32, BB), dim3(32, 8)>>>(x);
    build_meta_kernel<<<(BB * K2C * HWSZ) / 256, 256>>>(offset);
    prep_w_kernel<<<(OO * KTOT / 2) / 256, 256>>>(weight);
    dconv_mma_kernel<<<BB * 64, 256>>>(out);
}